// round 12
// baseline (speedup 1.0000x reference)
#include <cuda_runtime.h>
#include <cstdint>
#include <math.h>

// Problem constants (fixed shapes from reference setup_inputs)
#define BB 4
#define NN 16384
#define DD 512
#define HH 256
#define K_SEL 11468      // min(max(int(N*0.7),128),N)
#define N_RAND 1146      // max(int(k*0.1),1)
#define N_TOP (K_SEL - N_RAND)       // 10322
#define N_REM (NN - N_TOP)           // 6062
#define N_BITS (BB * N_REM)          // 24248 uniform samples (flattened)

#define M2 (DD / 4)                  // 128 four-k groups

// -------------------- device scratch (no allocations allowed) --------------------
__device__ float g_raw[BB * NN];
__device__ unsigned g_tkeys[BB * NN];
__device__ unsigned char g_topflag[BB * NN];
__device__ unsigned g_rkeys[BB * N_REM];
__device__ unsigned char g_possel[BB * N_REM];
__device__ int g_selidx[BB * K_SEL];
// packed weights: PV[m2*HH + t] = (Wv[4m2,t], Wv[4m2+1,t], Wv[4m2+2,t], Wv[4m2+3,t])
__device__ ulonglong2 g_PV[M2 * HH];
__device__ ulonglong2 g_PU[M2 * HH];

// ==================== 0) weight pre-pack ====================
__global__ void prepack_kernel(const float* __restrict__ Wv, const float* __restrict__ Wu)
{
    const int j = blockIdx.x * blockDim.x + threadIdx.x;   // 0 .. M2*HH-1
    if (j >= M2 * HH) return;
    const int m2 = j >> 8;         // /HH
    const int t = j & 255;
    float* dv = (float*)&g_PV[j];
    float* du = (float*)&g_PU[j];
#pragma unroll
    for (int e = 0; e < 4; e++) {
        dv[e] = Wv[(size_t)(4 * m2 + e) * HH + t];
        du[e] = Wu[(size_t)(4 * m2 + e) * HH + t];
    }
}

// ==================== 1) scoring ====================
// raw[b,n] = sum_h tanh(xWv)*sig(xWu)*wa + ba, fp32, packed fma.rn.f32x2 over
// even/odd k-parity partial accumulators (bit-identical to R10 ordering).
#define SROWS 32
__global__ __launch_bounds__(512) void score_kernel(
    const float* __restrict__ feat,
    const float* __restrict__ bv, const float* __restrict__ bu,
    const float* __restrict__ wa, const float* __restrict__ ba)
{
    extern __shared__ float smemf[];
    float* xs = smemf;                    // 32*512 floats = 64 KB
    float* red = smemf + SROWS * DD;      // 32*8 floats

    const int tid = threadIdx.x;
    const int g = tid >> 8;               // row group 0/1
    const int t = tid & 255;              // h index
    const int row0 = blockIdx.x * SROWS;

    // cooperative load 32x512 floats (coalesced float4)
    {
        const float4* src = (const float4*)(feat + (size_t)row0 * DD);
        float4* dst = (float4*)xs;
        for (int i = tid; i < SROWS * DD / 4; i += 512) dst[i] = src[i];
    }
    __syncthreads();

    unsigned long long accv[16], accu[16];
#pragma unroll
    for (int r = 0; r < 16; r++) { accv[r] = 0ull; accu[r] = 0ull; }

    const ulonglong2* __restrict__ pv = g_PV + t;
    const ulonglong2* __restrict__ pu = g_PU + t;
    const float* xbase = xs + (g * 16) * DD;

    // double-buffered weight fetch
    ulonglong2 wv = __ldg(pv);
    ulonglong2 wu = __ldg(pu);
    for (int m2 = 0; m2 < M2; m2++) {
        ulonglong2 wv_n, wu_n;
        if (m2 + 1 < M2) {
            wv_n = __ldg(pv + (m2 + 1) * HH);
            wu_n = __ldg(pu + (m2 + 1) * HH);
        }
#pragma unroll
        for (int r = 0; r < 16; r++) {
            const ulonglong2 x2 = *(const ulonglong2*)&xbase[r * DD + 4 * m2];
            asm("fma.rn.f32x2 %0, %1, %2, %0;" : "+l"(accv[r]) : "l"(x2.x), "l"(wv.x));
            asm("fma.rn.f32x2 %0, %1, %2, %0;" : "+l"(accv[r]) : "l"(x2.y), "l"(wv.y));
            asm("fma.rn.f32x2 %0, %1, %2, %0;" : "+l"(accu[r]) : "l"(x2.x), "l"(wu.x));
            asm("fma.rn.f32x2 %0, %1, %2, %0;" : "+l"(accu[r]) : "l"(x2.y), "l"(wu.y));
        }
        wv = wv_n; wu = wu_n;
    }

    const float bvv = bv[t], buu = bu[t], w = wa[t];
    float vals[16];
#pragma unroll
    for (int r = 0; r < 16; r++) {
        float vlo, vhi, ulo, uhi;
        asm("mov.b64 {%0, %1}, %2;" : "=f"(vlo), "=f"(vhi) : "l"(accv[r]));
        asm("mov.b64 {%0, %1}, %2;" : "=f"(ulo), "=f"(uhi) : "l"(accu[r]));
        const float av = vlo + vhi;
        const float au = ulo + uhi;
        const float hv = tanhf(av + bvv);
        const float hu = 1.0f / (1.0f + expf(-(au + buu)));
        vals[r] = hv * hu * w;
    }

    const int lane = t & 31;
    const int wgrp = (tid >> 5) & 7;      // warp index within row group
#pragma unroll
    for (int r = 0; r < 16; r++) {
        float v = vals[r];
        for (int o = 16; o > 0; o >>= 1) v += __shfl_down_sync(0xffffffffu, v, o);
        if (lane == 0) red[(g * 16 + r) * 8 + wgrp] = v;
    }
    __syncthreads();
    if (tid < SROWS) {
        float s = 0.f;
#pragma unroll
        for (int ww = 0; ww < 8; ww++) s += red[tid * 8 + ww];
        g_raw[row0 + tid] = s + ba[0];
    }
}

// ==================== 2) softmax (writes attn output) + orderable keys ====================
__global__ void softmax_keys_kernel(float* attn_out)
{
    const int b = blockIdx.x;
    const float* raw = g_raw + (size_t)b * NN;
    __shared__ float sm[32];
    __shared__ float s_bcast;
    const int tid = threadIdx.x, lane = tid & 31, wid = tid >> 5;

    float mx = -3.0e38f;
    for (int i = tid; i < NN; i += 1024) mx = fmaxf(mx, raw[i]);
    for (int o = 16; o > 0; o >>= 1) mx = fmaxf(mx, __shfl_down_sync(0xffffffffu, mx, o));
    if (lane == 0) sm[wid] = mx;
    __syncthreads();
    if (wid == 0) {
        float v = sm[lane];
        for (int o = 16; o > 0; o >>= 1) v = fmaxf(v, __shfl_down_sync(0xffffffffu, v, o));
        if (lane == 0) s_bcast = v;
    }
    __syncthreads();
    const float M = s_bcast;
    __syncthreads();

    float sum = 0.f;
    for (int i = tid; i < NN; i += 1024) sum += expf(raw[i] - M);
    for (int o = 16; o > 0; o >>= 1) sum += __shfl_down_sync(0xffffffffu, sum, o);
    if (lane == 0) sm[wid] = sum;
    __syncthreads();
    if (wid == 0) {
        float v = sm[lane];
        for (int o = 16; o > 0; o >>= 1) v += __shfl_down_sync(0xffffffffu, v, o);
        if (lane == 0) s_bcast = v;
    }
    __syncthreads();
    const float S = s_bcast;
    const float invS = 1.0f / S;

    for (int i = tid; i < NN; i += 1024) {
        const float r = raw[i];
        if (attn_out) attn_out[(size_t)b * NN + i] = expf(r - M) * invS;
        const unsigned bits = __float_as_uint(r);
        const unsigned u = (bits & 0x80000000u) ? ~bits : (bits | 0x80000000u);
        g_tkeys[(size_t)b * NN + i] = ~u;  // ascending == raw descending
    }
}

// ==================== block exclusive scan (exactly 1024 threads) ====================
__device__ __forceinline__ int block_excl_scan_1024(int val, int* ws)
{
    const int tid = threadIdx.x, lane = tid & 31, wid = tid >> 5;
    __syncthreads();
    int v = val;
#pragma unroll
    for (int o = 1; o < 32; o <<= 1) {
        int t = __shfl_up_sync(0xffffffffu, v, o);
        if (lane >= o) v += t;
    }
    if (lane == 31) ws[wid] = v;
    __syncthreads();
    if (wid == 0) {
        int s = ws[lane];
#pragma unroll
        for (int o = 1; o < 32; o <<= 1) {
            int t = __shfl_up_sync(0xffffffffu, s, o);
            if (lane >= o) s += t;
        }
        ws[lane] = s;
    }
    __syncthreads();
    const int wbase = (wid > 0) ? ws[wid - 1] : 0;
    return wbase + (v - val);
}

// ==================== 3) radix select: flag n smallest keys (tie -> lower index) ====
template <int L, int NSEL>
__device__ void radix_select_body(const unsigned* __restrict__ keys, unsigned char* __restrict__ flags)
{
    __shared__ unsigned hist[256];
    __shared__ unsigned s_prefix;
    __shared__ int s_need;
    __shared__ int ws[32];

    const int tid = threadIdx.x;
    unsigned prefix = 0, maskbits = 0;
    int need = NSEL;

#pragma unroll
    for (int pass = 0; pass < 4; pass++) {
        const int shift = 24 - 8 * pass;
        if (tid < 256) hist[tid] = 0;
        __syncthreads();
        for (int i = tid; i < L; i += 1024) {
            const unsigned k = keys[i];
            if ((k & maskbits) == prefix) atomicAdd(&hist[(k >> shift) & 0xFFu], 1u);
        }
        __syncthreads();
        if (tid == 0) {
            unsigned run = 0; int d = 0;
            for (; d < 256; d++) {
                if (run + hist[d] >= (unsigned)need) break;
                run += hist[d];
            }
            s_prefix = prefix | ((unsigned)d << shift);
            s_need = need - (int)run;
        }
        __syncthreads();
        prefix = s_prefix;
        need = s_need;
        maskbits |= (0xFFu << shift);
        __syncthreads();
    }
    const unsigned T = prefix;

    const int chunk = (L + 1023) / 1024;
    const int start = tid * chunk;
    int cnt = 0;
    for (int e = 0; e < chunk; e++) {
        const int i = start + e;
        if (i < L && keys[i] == T) cnt++;
    }
    const int base = block_excl_scan_1024(cnt, ws);
    int seen = 0;
    for (int e = 0; e < chunk; e++) {
        const int i = start + e;
        if (i < L) {
            const unsigned k = keys[i];
            unsigned char f = 0;
            if (k < T) f = 1;
            else if (k == T) {
                if (base + seen < need) f = 1;
                seen++;
            }
            flags[i] = f;
        }
    }
}

__global__ void topk_select_kernel()
{
    radix_select_body<NN, N_TOP>(g_tkeys + (size_t)blockIdx.x * NN,
                                 g_topflag + (size_t)blockIdx.x * NN);
}
__global__ void rand_select_kernel()
{
    radix_select_body<N_REM, N_RAND>(g_rkeys + (size_t)blockIdx.x * N_REM,
                                     g_possel + (size_t)blockIdx.x * N_REM);
}

// ==================== 4) JAX threefry2x32, PARTITIONABLE mode ====================
__device__ __forceinline__ unsigned rotl32(unsigned x, int r) { return (x << r) | (x >> (32 - r)); }

__global__ void threefry_kernel()
{
    const int i = blockIdx.x * blockDim.x + threadIdx.x;
    if (i >= N_BITS) return;
    const unsigned k0 = 0u, k1 = 42u;
    const unsigned k2 = k0 ^ k1 ^ 0x1BD11BDAu;
    unsigned x0 = 0u;
    unsigned x1 = (unsigned)i;
    x0 += k0; x1 += k1;

#define TF_ROUND(r) { x0 += x1; x1 = rotl32(x1, r); x1 ^= x0; }
    TF_ROUND(13) TF_ROUND(15) TF_ROUND(26) TF_ROUND(6)
    x0 += k1; x1 += k2 + 1u;
    TF_ROUND(17) TF_ROUND(29) TF_ROUND(16) TF_ROUND(24)
    x0 += k2; x1 += k0 + 2u;
    TF_ROUND(13) TF_ROUND(15) TF_ROUND(26) TF_ROUND(6)
    x0 += k0; x1 += k1 + 3u;
    TF_ROUND(17) TF_ROUND(29) TF_ROUND(16) TF_ROUND(24)
    x0 += k1; x1 += k2 + 4u;
    TF_ROUND(13) TF_ROUND(15) TF_ROUND(26) TF_ROUND(6)
    x0 += k2; x1 += k0 + 5u;
#undef TF_ROUND

    g_rkeys[i] = (x0 ^ x1) >> 9;
}

// ==================== 5) combine: sel flags -> ascending sel_idx ====================
__global__ void combine_kernel(float* idx_out)
{
    const int b = blockIdx.x;
    const unsigned char* __restrict__ top = g_topflag + (size_t)b * NN;
    const unsigned char* __restrict__ psel = g_possel + (size_t)b * N_REM;
    __shared__ int ws[32];
    const int tid = threadIdx.x;
    const int chunk = NN / 1024; // 16
    const int start = tid * chunk;

    unsigned char tloc[16];
    int cntN = 0;
#pragma unroll
    for (int e = 0; e < 16; e++) {
        tloc[e] = top[start + e];
        if (!tloc[e]) cntN++;
    }
    const int baseN = block_excl_scan_1024(cntN, ws);

    int selbits = 0, cntS = 0, seenN = 0;
#pragma unroll
    for (int e = 0; e < 16; e++) {
        bool s;
        if (tloc[e]) s = true;
        else { s = (psel[baseN + seenN] != 0); seenN++; }
        if (s) { selbits |= (1 << e); cntS++; }
    }
    const int baseS = block_excl_scan_1024(cntS, ws);

    int seenS = 0;
#pragma unroll
    for (int e = 0; e < 16; e++) {
        if ((selbits >> e) & 1) {
            const int i = start + e;
            const int pos = baseS + seenS;
            seenS++;
            g_selidx[(size_t)b * K_SEL + pos] = i;
            if (idx_out) idx_out[(size_t)b * K_SEL + pos] = (float)i;
        }
    }
}

// ==================== 6) gather selected rows ====================
__global__ void gather_kernel(const float* __restrict__ feat, float* __restrict__ out)
{
    const int r = blockIdx.x;
    const int b = blockIdx.y;
    const int idx = g_selidx[(size_t)b * K_SEL + r];
    const float4* __restrict__ src = (const float4*)(feat + ((size_t)b * NN + idx) * DD);
    float4* __restrict__ dst = (float4*)(out + ((size_t)b * K_SEL + r) * DD);
    dst[threadIdx.x] = src[threadIdx.x];
}

// ==================== launch ====================
extern "C" void kernel_launch(void* const* d_in, const int* in_sizes, int n_in,
                              void* d_out, int out_size)
{
    // --- role detection by element count (robust to metadata ordering) ---
    int idx_feat = -1, idx_scalar = -1;
    int mats[2] = {-1, -1}; int nm = 0;
    int vecs[3] = {-1, -1, -1}; int nv = 0;
    for (int i = 0; i < n_in; i++) {
        const int s = in_sizes[i];
        if (s == 33554432) idx_feat = i;
        else if (s == 131072 && nm < 2) mats[nm++] = i;
        else if (s == 256 && nv < 3) vecs[nv++] = i;
        else if (s == 1) idx_scalar = i;
    }

    const float *feat, *Wv, *bv, *Wu, *bu, *wa, *ba;
    if (idx_feat >= 0 && nm == 2 && nv == 3 && idx_scalar >= 0) {
        feat = (const float*)d_in[idx_feat];
        ba   = (const float*)d_in[idx_scalar];
        wa   = (const float*)d_in[vecs[2]];
        bv   = (const float*)d_in[vecs[0]];
        bu   = (const float*)d_in[vecs[1]];
        if (idx_feat == 0) {
            Wv = (const float*)d_in[mats[0]];
            Wu = (const float*)d_in[mats[1]];
        } else {
            Wu = (const float*)d_in[mats[0]];
            Wv = (const float*)d_in[mats[1]];
        }
    } else {
        feat = (const float*)d_in[0];
        Wv   = (const float*)d_in[1];
        bv   = (const float*)d_in[2];
        Wu   = (const float*)d_in[3];
        bu   = (const float*)d_in[4];
        wa   = (const float*)d_in[5];
        ba   = (const float*)d_in[6];
    }

    float* out = (float*)d_out;

    const long long SELN = (long long)BB * K_SEL * DD;
    const long long ATTN = (long long)BB * NN;
    const long long IDXN = (long long)BB * K_SEL;

    float* attn_out = ((long long)out_size >= SELN + ATTN) ? out + SELN : nullptr;
    float* idx_out  = ((long long)out_size >= SELN + ATTN + IDXN) ? out + SELN + ATTN : nullptr;

    const int smem_bytes = SROWS * DD * 4 + SROWS * 8 * 4;   // 66560
    static int attr_done = 0;
    if (!attr_done) {
        cudaFuncSetAttribute(score_kernel,
                             cudaFuncAttributeMaxDynamicSharedMemorySize, smem_bytes);
        attr_done = 1;
    }

    prepack_kernel<<<(M2 * HH + 255) / 256, 256>>>(Wv, Wu);
    score_kernel<<<(BB * NN) / SROWS, 512, smem_bytes>>>(feat, bv, bu, wa, ba);
    softmax_keys_kernel<<<BB, 1024>>>(attn_out);
    topk_select_kernel<<<BB, 1024>>>();
    threefry_kernel<<<(N_BITS + 255) / 256, 256>>>();
    rand_select_kernel<<<BB, 1024>>>();
    combine_kernel<<<BB, 1024>>>(idx_out);
    {
        dim3 grid(K_SEL, BB);
        gather_kernel<<<grid, 128>>>(feat, out);
    }
}

// round 15
// speedup vs baseline: 1.7433x; 1.7433x over previous
#include <cuda_runtime.h>
#include <cuda_bf16.h>
#include <cstdint>
#include <math.h>

// Problem constants
#define BB 4
#define NN 16384
#define DD 512
#define HH 256
#define K_SEL 11468
#define N_RAND 1146
#define N_TOP (K_SEL - N_RAND)       // 10322
#define N_REM (NN - N_TOP)           // 6062
#define N_BITS (BB * N_REM)          // 24248

#define MROWS 128                    // rows per CTA
#define KC 64                        // k per chunk
#define NCHUNKS (DD / KC)            // 8
#define NPASS 2                      // stacked-N halves of 256
#define THREADS 512

// dynamic smem offsets (all 1KB aligned regions)
#define SM_AH 0                      // A hi: 128 x 128B (SW128)
#define SM_AL 16384                  // A lo
#define SM_BH 32768                  // B hi: 256 x 128B
#define SM_BL 65536                  // B lo
#define SM_V  98304                  // 128x128 fp32 v-preacts (64KB)
#define SM_SLOT (SM_V + 65536)       // 128x2 fp32 row partials
#define SM_BIAS (SM_SLOT + 1024)     // bv|bu|wa (3x256 fp32)
#define SMEM_TOTAL (SM_BIAS + 3 * 256 * 4)   // 167936

// -------------------- device scratch --------------------
__device__ float g_raw[BB * NN];
__device__ unsigned g_tkeys[BB * NN];
__device__ unsigned char g_topflag[BB * NN];
__device__ unsigned g_rkeys[BB * N_REM];
__device__ unsigned char g_possel[BB * N_REM];
__device__ int g_selidx[BB * K_SEL];
// B^T stacked splits: row n in [0,512): pass p=n/256, j=n%256,
//   h = p*128 + (j&127); j<128 -> Wv col h, else Wu col h. B[n][k] = W[k][h].
__device__ __nv_bfloat16 g_Bh[512 * DD];
__device__ __nv_bfloat16 g_Bl[512 * DD];

__device__ __forceinline__ uint32_t smem_u32(const void* p) {
    uint32_t a;
    asm("{ .reg .u64 t; cvta.to.shared.u64 t, %1; cvt.u32.u64 %0, t; }" : "=r"(a) : "l"(p));
    return a;
}
__device__ __forceinline__ uint32_t swz(uint32_t off) { return off ^ ((off >> 3) & 0x70u); }

__device__ __forceinline__ void ldsm_x4(uint32_t addr, uint32_t* r) {
    asm volatile("ldmatrix.sync.aligned.m8n8.x4.shared.b16 {%0,%1,%2,%3}, [%4];"
        : "=r"(r[0]), "=r"(r[1]), "=r"(r[2]), "=r"(r[3]) : "r"(addr));
}
#define MMA_BF16(C, A, b0, b1) \
    asm volatile("mma.sync.aligned.m16n8k16.row.col.f32.bf16.bf16.f32 " \
        "{%0,%1,%2,%3}, {%4,%5,%6,%7}, {%8,%9}, {%0,%1,%2,%3};" \
        : "+f"((C)[0]), "+f"((C)[1]), "+f"((C)[2]), "+f"((C)[3]) \
        : "r"((A)[0]), "r"((A)[1]), "r"((A)[2]), "r"((A)[3]), "r"(b0), "r"(b1))

// ==================== 0) weight split/transpose prepack ====================
__global__ void prepack_kernel(const float* __restrict__ Wv, const float* __restrict__ Wu)
{
    const int idx = blockIdx.x * blockDim.x + threadIdx.x;   // n*512 + k
    if (idx >= 512 * DD) return;
    const int n = idx >> 9, k = idx & 511;
    const int p = n >> 8, j = n & 255;
    const int h = p * 128 + (j & 127);
    const float w = (j < 128) ? Wv[(size_t)k * HH + h] : Wu[(size_t)k * HH + h];
    const __nv_bfloat16 hi = __float2bfloat16(w);
    const float r = w - __bfloat162float(hi);
    g_Bh[idx] = hi;
    g_Bl[idx] = __float2bfloat16(r);
}

// ==================== 1) scoring via mma.sync bf16 (3-term split) ====================
__global__ __launch_bounds__(THREADS) void score_kernel(
    const float* __restrict__ feat,
    const float* __restrict__ bv, const float* __restrict__ bu,
    const float* __restrict__ wa, const float* __restrict__ ba)
{
    extern __shared__ char smem[];
    const uint32_t sb = smem_u32(smem);
    const int tid = threadIdx.x;
    const int w = tid >> 5, lane = tid & 31;
    const int wm = w & 3, wn = w >> 2;          // warp grid 4(M) x 4(N)
    const int g = lane >> 2, tig = lane & 3;
    const int sub = lane >> 3, lr = lane & 7;   // ldmatrix lane decomposition
    const int row0 = blockIdx.x * MROWS;

    float* sbias = (float*)(smem + SM_BIAS);
    float* slot = (float*)(smem + SM_SLOT);
    float* vbuf = (float*)(smem + SM_V);
    if (tid < 256) {
        sbias[tid] = bv[tid];
        sbias[256 + tid] = bu[tid];
        sbias[512 + tid] = wa[tid];
        slot[tid] = 0.0f;
    }

    for (int pass = 0; pass < NPASS; pass++) {
        float acc[2][8][4];
#pragma unroll
        for (int mt = 0; mt < 2; mt++)
#pragma unroll
            for (int nj = 0; nj < 8; nj++)
#pragma unroll
                for (int e = 0; e < 4; e++) acc[mt][nj][e] = 0.0f;

        for (int c = 0; c < NCHUNKS; c++) {
            __syncthreads();
            // fill A splits (128 rows x 64 k), SW128 rows of 128B
            for (int it = tid; it < MROWS * 16; it += THREADS) {
                const int r = it >> 4, q = it & 15;
                const float4 v = *(const float4*)(feat + (size_t)(row0 + r) * DD + c * KC + q * 4);
                const float xv[4] = { v.x, v.y, v.z, v.w };
                unsigned long long ph = 0, pl = 0;
#pragma unroll
                for (int e = 0; e < 4; e++) {
                    const float x = xv[e];
                    const __nv_bfloat16 h16 = __float2bfloat16(x);
                    const float rr = x - __bfloat162float(h16);
                    const __nv_bfloat16 l16 = __float2bfloat16(rr);
                    ph |= (unsigned long long)__bfloat16_as_ushort(h16) << (16 * e);
                    pl |= (unsigned long long)__bfloat16_as_ushort(l16) << (16 * e);
                }
                const uint32_t off = swz((uint32_t)(r * 128 + q * 8));
                *(unsigned long long*)(smem + SM_AH + off) = ph;
                *(unsigned long long*)(smem + SM_AL + off) = pl;
            }
            // fill B splits (256 stacked rows x 64 k)
            {
                const size_t base = ((size_t)pass * 256) * DD + c * KC;
                for (int it = tid; it < 256 * 8; it += THREADS) {
                    const int n = it >> 3, u = it & 7;
                    const uint4 vh = *(const uint4*)((const char*)(g_Bh + base + (size_t)n * DD) + u * 16);
                    const uint4 vl = *(const uint4*)((const char*)(g_Bl + base + (size_t)n * DD) + u * 16);
                    const uint32_t off = swz((uint32_t)(n * 128 + u * 16));
                    *(uint4*)(smem + SM_BH + off) = vh;
                    *(uint4*)(smem + SM_BL + off) = vl;
                }
            }
            __syncthreads();

#pragma unroll
            for (int ks = 0; ks < 4; ks++) {
                uint32_t a[2][2][4];
#pragma unroll
                for (int mt = 0; mt < 2; mt++) {
                    const int row = wm * 32 + mt * 16 + lr + (sub & 1) * 8;
                    const int kk = ks * 16 + (sub >> 1) * 8;
                    const uint32_t off = swz((uint32_t)(row * 128 + kk * 2));
                    ldsm_x4(sb + SM_AH + off, a[0][mt]);
                    ldsm_x4(sb + SM_AL + off, a[1][mt]);
                }
#pragma unroll
                for (int ng = 0; ng < 4; ng++) {
                    const int nrow = wn * 64 + ng * 16 + lr + (sub & 1) * 8;
                    const int kk = ks * 16 + (sub >> 1) * 8;
                    const uint32_t off = swz((uint32_t)(nrow * 128 + kk * 2));
                    uint32_t bh[4], bl[4];
                    ldsm_x4(sb + SM_BH + off, bh);
                    ldsm_x4(sb + SM_BL + off, bl);
#pragma unroll
                    for (int mt = 0; mt < 2; mt++) {
                        MMA_BF16(acc[mt][ng * 2 + 0], a[0][mt], bh[0], bh[2]);
                        MMA_BF16(acc[mt][ng * 2 + 0], a[0][mt], bl[0], bl[2]);
                        MMA_BF16(acc[mt][ng * 2 + 0], a[1][mt], bh[0], bh[2]);
                        MMA_BF16(acc[mt][ng * 2 + 1], a[0][mt], bh[1], bh[3]);
                        MMA_BF16(acc[mt][ng * 2 + 1], a[0][mt], bl[1], bl[3]);
                        MMA_BF16(acc[mt][ng * 2 + 1], a[1][mt], bh[1], bh[3]);
                    }
                }
            }
        }

        // ---- epilogue for this pass ----
        __syncthreads();
        if (wn < 2) {
            // stage v-half preacts to smem
#pragma unroll
            for (int mt = 0; mt < 2; mt++)
#pragma unroll
                for (int nj = 0; nj < 8; nj++) {
                    const int j = wn * 64 + nj * 8 + tig * 2;
                    const int m = wm * 32 + mt * 16 + g;
                    vbuf[m * 128 + j] = acc[mt][nj][0];
                    vbuf[m * 128 + j + 1] = acc[mt][nj][1];
                    vbuf[(m + 8) * 128 + j] = acc[mt][nj][2];
                    vbuf[(m + 8) * 128 + j + 1] = acc[mt][nj][3];
                }
        }
        __syncthreads();
        if (wn >= 2) {
            float rp0[2] = { 0.f, 0.f }, rp1[2] = { 0.f, 0.f };
#pragma unroll
            for (int mt = 0; mt < 2; mt++) {
                const int m = wm * 32 + mt * 16 + g;
#pragma unroll
                for (int nj = 0; nj < 8; nj++) {
                    const int j = (wn - 2) * 64 + nj * 8 + tig * 2;
                    const int h = pass * 128 + j;
#pragma unroll
                    for (int e = 0; e < 2; e++) {
                        const float bvh = sbias[h + e];
                        const float buh = sbias[256 + h + e];
                        const float wah = sbias[512 + h + e];
                        const float hv0 = tanhf(vbuf[m * 128 + j + e] + bvh);
                        const float hu0 = 1.0f / (1.0f + expf(-(acc[mt][nj][e] + buh)));
                        rp0[mt] += hv0 * hu0 * wah;
                        const float hv1 = tanhf(vbuf[(m + 8) * 128 + j + e] + bvh);
                        const float hu1 = 1.0f / (1.0f + expf(-(acc[mt][nj][2 + e] + buh)));
                        rp1[mt] += hv1 * hu1 * wah;
                    }
                }
            }
#pragma unroll
            for (int mt = 0; mt < 2; mt++) {
                float v0 = rp0[mt], v1 = rp1[mt];
                v0 += __shfl_down_sync(0xffffffffu, v0, 2);
                v0 += __shfl_down_sync(0xffffffffu, v0, 1);
                v1 += __shfl_down_sync(0xffffffffu, v1, 2);
                v1 += __shfl_down_sync(0xffffffffu, v1, 1);
                if (tig == 0) {
                    const int m = wm * 32 + mt * 16 + g;
                    slot[m * 2 + (wn - 2)] += v0;          // unique writer per slot
                    slot[(m + 8) * 2 + (wn - 2)] += v1;
                }
            }
        }
    }

    __syncthreads();
    if (tid < MROWS)
        g_raw[row0 + tid] = slot[tid * 2] + slot[tid * 2 + 1] + ba[0];
}

// ==================== 2) softmax + orderable keys ====================
__global__ void softmax_keys_kernel(float* attn_out)
{
    const int b = blockIdx.x;
    const float* raw = g_raw + (size_t)b * NN;
    __shared__ float sm[32];
    __shared__ float s_bcast;
    const int tid = threadIdx.x, lane = tid & 31, wid = tid >> 5;

    float mx = -3.0e38f;
    for (int i = tid; i < NN; i += 1024) mx = fmaxf(mx, raw[i]);
    for (int o = 16; o > 0; o >>= 1) mx = fmaxf(mx, __shfl_down_sync(0xffffffffu, mx, o));
    if (lane == 0) sm[wid] = mx;
    __syncthreads();
    if (wid == 0) {
        float v = sm[lane];
        for (int o = 16; o > 0; o >>= 1) v = fmaxf(v, __shfl_down_sync(0xffffffffu, v, o));
        if (lane == 0) s_bcast = v;
    }
    __syncthreads();
    const float M = s_bcast;
    __syncthreads();

    float sum = 0.f;
    for (int i = tid; i < NN; i += 1024) sum += expf(raw[i] - M);
    for (int o = 16; o > 0; o >>= 1) sum += __shfl_down_sync(0xffffffffu, sum, o);
    if (lane == 0) sm[wid] = sum;
    __syncthreads();
    if (wid == 0) {
        float v = sm[lane];
        for (int o = 16; o > 0; o >>= 1) v += __shfl_down_sync(0xffffffffu, v, o);
        if (lane == 0) s_bcast = v;
    }
    __syncthreads();
    const float S = s_bcast;
    const float invS = 1.0f / S;

    for (int i = tid; i < NN; i += 1024) {
        const float r = raw[i];
        if (attn_out) attn_out[(size_t)b * NN + i] = expf(r - M) * invS;
        const unsigned bits = __float_as_uint(r);
        const unsigned u = (bits & 0x80000000u) ? ~bits : (bits | 0x80000000u);
        g_tkeys[(size_t)b * NN + i] = ~u;
    }
}

// ==================== scan helper ====================
__device__ __forceinline__ int block_excl_scan_1024(int val, int* ws)
{
    const int tid = threadIdx.x, lane = tid & 31, wid = tid >> 5;
    __syncthreads();
    int v = val;
#pragma unroll
    for (int o = 1; o < 32; o <<= 1) {
        int t = __shfl_up_sync(0xffffffffu, v, o);
        if (lane >= o) v += t;
    }
    if (lane == 31) ws[wid] = v;
    __syncthreads();
    if (wid == 0) {
        int s = ws[lane];
#pragma unroll
        for (int o = 1; o < 32; o <<= 1) {
            int t = __shfl_up_sync(0xffffffffu, s, o);
            if (lane >= o) s += t;
        }
        ws[lane] = s;
    }
    __syncthreads();
    const int wbase = (wid > 0) ? ws[wid - 1] : 0;
    return wbase + (v - val);
}

// ==================== 3) radix select ====================
template <int L, int NSEL>
__device__ void radix_select_body(const unsigned* __restrict__ keys, unsigned char* __restrict__ flags)
{
    __shared__ unsigned hist[256];
    __shared__ unsigned s_prefix;
    __shared__ int s_need;
    __shared__ int ws[32];

    const int tid = threadIdx.x;
    unsigned prefix = 0, maskbits = 0;
    int need = NSEL;

#pragma unroll
    for (int pass = 0; pass < 4; pass++) {
        const int shift = 24 - 8 * pass;
        if (tid < 256) hist[tid] = 0;
        __syncthreads();
        for (int i = tid; i < L; i += 1024) {
            const unsigned k = keys[i];
            if ((k & maskbits) == prefix) atomicAdd(&hist[(k >> shift) & 0xFFu], 1u);
        }
        __syncthreads();
        if (tid == 0) {
            unsigned run = 0; int d = 0;
            for (; d < 256; d++) {
                if (run + hist[d] >= (unsigned)need) break;
                run += hist[d];
            }
            s_prefix = prefix | ((unsigned)d << shift);
            s_need = need - (int)run;
        }
        __syncthreads();
        prefix = s_prefix;
        need = s_need;
        maskbits |= (0xFFu << shift);
        __syncthreads();
    }
    const unsigned T = prefix;

    const int chunk = (L + 1023) / 1024;
    const int start = tid * chunk;
    int cnt = 0;
    for (int e = 0; e < chunk; e++) {
        const int i = start + e;
        if (i < L && keys[i] == T) cnt++;
    }
    const int base = block_excl_scan_1024(cnt, ws);
    int seen = 0;
    for (int e = 0; e < chunk; e++) {
        const int i = start + e;
        if (i < L) {
            const unsigned k = keys[i];
            unsigned char f = 0;
            if (k < T) f = 1;
            else if (k == T) {
                if (base + seen < need) f = 1;
                seen++;
            }
            flags[i] = f;
        }
    }
}

__global__ void topk_select_kernel()
{
    radix_select_body<NN, N_TOP>(g_tkeys + (size_t)blockIdx.x * NN,
                                 g_topflag + (size_t)blockIdx.x * NN);
}
__global__ void rand_select_kernel()
{
    radix_select_body<N_REM, N_RAND>(g_rkeys + (size_t)blockIdx.x * N_REM,
                                     g_possel + (size_t)blockIdx.x * N_REM);
}

// ==================== 4) threefry (partitionable) ====================
__device__ __forceinline__ unsigned rotl32(unsigned x, int r) { return (x << r) | (x >> (32 - r)); }

__global__ void threefry_kernel()
{
    const int i = blockIdx.x * blockDim.x + threadIdx.x;
    if (i >= N_BITS) return;
    const unsigned k0 = 0u, k1 = 42u;
    const unsigned k2 = k0 ^ k1 ^ 0x1BD11BDAu;
    unsigned x0 = 0u;
    unsigned x1 = (unsigned)i;
    x0 += k0; x1 += k1;

#define TF_ROUND(r) { x0 += x1; x1 = rotl32(x1, r); x1 ^= x0; }
    TF_ROUND(13) TF_ROUND(15) TF_ROUND(26) TF_ROUND(6)
    x0 += k1; x1 += k2 + 1u;
    TF_ROUND(17) TF_ROUND(29) TF_ROUND(16) TF_ROUND(24)
    x0 += k2; x1 += k0 + 2u;
    TF_ROUND(13) TF_ROUND(15) TF_ROUND(26) TF_ROUND(6)
    x0 += k0; x1 += k1 + 3u;
    TF_ROUND(17) TF_ROUND(29) TF_ROUND(16) TF_ROUND(24)
    x0 += k1; x1 += k2 + 4u;
    TF_ROUND(13) TF_ROUND(15) TF_ROUND(26) TF_ROUND(6)
    x0 += k2; x1 += k0 + 5u;
#undef TF_ROUND

    g_rkeys[i] = (x0 ^ x1) >> 9;
}

// ==================== 5) combine ====================
__global__ void combine_kernel(float* idx_out)
{
    const int b = blockIdx.x;
    const unsigned char* __restrict__ top = g_topflag + (size_t)b * NN;
    const unsigned char* __restrict__ psel = g_possel + (size_t)b * N_REM;
    __shared__ int ws[32];
    const int tid = threadIdx.x;
    const int start = tid * 16;

    unsigned char tloc[16];
    int cntN = 0;
#pragma unroll
    for (int e = 0; e < 16; e++) {
        tloc[e] = top[start + e];
        if (!tloc[e]) cntN++;
    }
    const int baseN = block_excl_scan_1024(cntN, ws);

    int selbits = 0, cntS = 0, seenN = 0;
#pragma unroll
    for (int e = 0; e < 16; e++) {
        bool s;
        if (tloc[e]) s = true;
        else { s = (psel[baseN + seenN] != 0); seenN++; }
        if (s) { selbits |= (1 << e); cntS++; }
    }
    const int baseS = block_excl_scan_1024(cntS, ws);

    int seenS = 0;
#pragma unroll
    for (int e = 0; e < 16; e++) {
        if ((selbits >> e) & 1) {
            const int i = start + e;
            const int pos = baseS + seenS;
            seenS++;
            g_selidx[(size_t)b * K_SEL + pos] = i;
            if (idx_out) idx_out[(size_t)b * K_SEL + pos] = (float)i;
        }
    }
}

// ==================== 6) gather ====================
__global__ void gather_kernel(const float* __restrict__ feat, float* __restrict__ out)
{
    const int r = blockIdx.x;
    const int b = blockIdx.y;
    const int idx = g_selidx[(size_t)b * K_SEL + r];
    const float4* __restrict__ src = (const float4*)(feat + ((size_t)b * NN + idx) * DD);
    float4* __restrict__ dst = (float4*)(out + ((size_t)b * K_SEL + r) * DD);
    dst[threadIdx.x] = src[threadIdx.x];
}

// ==================== launch ====================
extern "C" void kernel_launch(void* const* d_in, const int* in_sizes, int n_in,
                              void* d_out, int out_size)
{
    int idx_feat = -1, idx_scalar = -1;
    int mats[2] = {-1, -1}; int nm = 0;
    int vecs[3] = {-1, -1, -1}; int nv = 0;
    for (int i = 0; i < n_in; i++) {
        const int s = in_sizes[i];
        if (s == 33554432) idx_feat = i;
        else if (s == 131072 && nm < 2) mats[nm++] = i;
        else if (s == 256 && nv < 3) vecs[nv++] = i;
        else if (s == 1) idx_scalar = i;
    }

    const float *feat, *Wv, *bv, *Wu, *bu, *wa, *ba;
    if (idx_feat >= 0 && nm == 2 && nv == 3 && idx_scalar >= 0) {
        feat = (const float*)d_in[idx_feat];
        ba   = (const float*)d_in[idx_scalar];
        wa   = (const float*)d_in[vecs[2]];
        bv   = (const float*)d_in[vecs[0]];
        bu   = (const float*)d_in[vecs[1]];
        if (idx_feat == 0) { Wv = (const float*)d_in[mats[0]]; Wu = (const float*)d_in[mats[1]]; }
        else               { Wu = (const float*)d_in[mats[0]]; Wv = (const float*)d_in[mats[1]]; }
    } else {
        feat = (const float*)d_in[0];
        Wv   = (const float*)d_in[1];
        bv   = (const float*)d_in[2];
        Wu   = (const float*)d_in[3];
        bu   = (const float*)d_in[4];
        wa   = (const float*)d_in[5];
        ba   = (const float*)d_in[6];
    }

    float* out = (float*)d_out;
    const long long SELN = (long long)BB * K_SEL * DD;
    const long long ATTN = (long long)BB * NN;
    const long long IDXN = (long long)BB * K_SEL;
    float* attn_out = ((long long)out_size >= SELN + ATTN) ? out + SELN : nullptr;
    float* idx_out  = ((long long)out_size >= SELN + ATTN + IDXN) ? out + SELN + ATTN : nullptr;

    static int attr_done = 0;
    if (!attr_done) {
        cudaFuncSetAttribute(score_kernel,
                             cudaFuncAttributeMaxDynamicSharedMemorySize, SMEM_TOTAL);
        attr_done = 1;
    }

    prepack_kernel<<<(512 * DD + 255) / 256, 256>>>(Wv, Wu);
    score_kernel<<<(BB * NN) / MROWS, THREADS, SMEM_TOTAL>>>(feat, bv, bu, wa, ba);
    softmax_keys_kernel<<<BB, 1024>>>(attn_out);
    topk_select_kernel<<<BB, 1024>>>();
    threefry_kernel<<<(N_BITS + 255) / 256, 256>>>();
    rand_select_kernel<<<BB, 1024>>>();
    combine_kernel<<<BB, 1024>>>(idx_out);
    {
        dim3 grid(K_SEL, BB);
        gather_kernel<<<grid, 128>>>(feat, out);
    }
}

// round 16
// speedup vs baseline: 2.1634x; 1.2409x over previous
#include <cuda_runtime.h>
#include <cuda_bf16.h>
#include <cstdint>
#include <math.h>

// Problem constants
#define BB 4
#define NN 16384
#define DD 512
#define HH 256
#define K_SEL 11468
#define N_RAND 1146
#define N_TOP (K_SEL - N_RAND)       // 10322
#define N_REM (NN - N_TOP)           // 6062
#define N_BITS (BB * N_REM)          // 24248

#define MROWS 128                    // rows per CTA
#define KC 64                        // k per stage
#define NCHUNKS (DD / KC)            // 8
#define NPASS 2                      // h-halves of 128 (256 interleaved N each)
#define NSTAGES (NPASS * NCHUNKS)    // 16
#define THREADS 512

// per-stage buffer: AH 16K | AL 16K | BH 32K | BL 32K = 96KB
#define STG_BYTES 98304
#define STG_AH 0
#define STG_AL 16384
#define STG_BH 32768
#define STG_BL 65536
#define SM_BIAS (2 * STG_BYTES)              // 3*256 fp32
#define SM_SLOT (SM_BIAS + 3 * 256 * 4)      // 128*8 fp32
#define SMEM_TOTAL (SM_SLOT + 128 * 8 * 4)   // 203776

// -------------------- device scratch --------------------
__device__ float g_raw[BB * NN];
__device__ unsigned g_tkeys[BB * NN];
__device__ unsigned char g_topflag[BB * NN];
__device__ unsigned g_rkeys[BB * N_REM];
__device__ unsigned char g_possel[BB * N_REM];
__device__ int g_selidx[BB * K_SEL];
// A splits: row-major [65536][512] bf16
__device__ __nv_bfloat16 g_Ah[(size_t)BB * NN * DD];
__device__ __nv_bfloat16 g_Al[(size_t)BB * NN * DD];
// B^T interleaved stacked splits: row n in [0,512): pass p=n>>8, j=n&255,
//   h = p*128 + (j>>1); even j -> Wv col h, odd j -> Wu col h. B[n][k]=W[k][h].
__device__ __nv_bfloat16 g_Bh[512 * DD];
__device__ __nv_bfloat16 g_Bl[512 * DD];

__device__ __forceinline__ uint32_t smem_u32(const void* p) {
    uint32_t a;
    asm("{ .reg .u64 t; cvta.to.shared.u64 t, %1; cvt.u32.u64 %0, t; }" : "=r"(a) : "l"(p));
    return a;
}
__device__ __forceinline__ uint32_t swz(uint32_t off) { return off ^ ((off >> 3) & 0x70u); }

__device__ __forceinline__ void ldsm_x4(uint32_t addr, uint32_t* r) {
    asm volatile("ldmatrix.sync.aligned.m8n8.x4.shared.b16 {%0,%1,%2,%3}, [%4];"
        : "=r"(r[0]), "=r"(r[1]), "=r"(r[2]), "=r"(r[3]) : "r"(addr));
}
#define MMA_BF16(C, A, b0, b1) \
    asm volatile("mma.sync.aligned.m16n8k16.row.col.f32.bf16.bf16.f32 " \
        "{%0,%1,%2,%3}, {%4,%5,%6,%7}, {%8,%9}, {%0,%1,%2,%3};" \
        : "+f"((C)[0]), "+f"((C)[1]), "+f"((C)[2]), "+f"((C)[3]) \
        : "r"((A)[0]), "r"((A)[1]), "r"((A)[2]), "r"((A)[3]), "r"(b0), "r"(b1))
#define CP_ASYNC16(dst, src) \
    asm volatile("cp.async.cg.shared.global [%0], [%1], 16;" :: "r"(dst), "l"(src) : "memory")
#define CP_COMMIT() asm volatile("cp.async.commit_group;" ::: "memory")

// ==================== 0a) feature split prepack ====================
__global__ void asplit_kernel(const float* __restrict__ feat)
{
    const size_t i4 = (size_t)blockIdx.x * blockDim.x + threadIdx.x;   // float4 index
    if (i4 >= (size_t)BB * NN * DD / 4) return;
    const float4 v = ((const float4*)feat)[i4];
    const float xv[4] = { v.x, v.y, v.z, v.w };
    unsigned long long ph = 0, pl = 0;
#pragma unroll
    for (int e = 0; e < 4; e++) {
        const float x = xv[e];
        const __nv_bfloat16 h = __float2bfloat16(x);
        const float r = x - __bfloat162float(h);
        const __nv_bfloat16 l = __float2bfloat16(r);
        ph |= (unsigned long long)__bfloat16_as_ushort(h) << (16 * e);
        pl |= (unsigned long long)__bfloat16_as_ushort(l) << (16 * e);
    }
    ((unsigned long long*)g_Ah)[i4] = ph;
    ((unsigned long long*)g_Al)[i4] = pl;
}

// ==================== 0b) weight split/transpose prepack (interleaved) ====
__global__ void prepack_kernel(const float* __restrict__ Wv, const float* __restrict__ Wu)
{
    const int idx = blockIdx.x * blockDim.x + threadIdx.x;   // n*512 + k
    if (idx >= 512 * DD) return;
    const int n = idx >> 9, k = idx & 511;
    const int p = n >> 8, j = n & 255;
    const int h = p * 128 + (j >> 1);
    const float w = ((j & 1) == 0) ? Wv[(size_t)k * HH + h] : Wu[(size_t)k * HH + h];
    const __nv_bfloat16 hi = __float2bfloat16(w);
    const float r = w - __bfloat162float(hi);
    g_Bh[idx] = hi;
    g_Bl[idx] = __float2bfloat16(r);
}

// ==================== 1) scoring: cp.async double-buffered mma.sync ====
__device__ __forceinline__ void fill_stage(char* smem, int bufidx, int stage, int row0, int tid)
{
    char* buf = smem + bufidx * STG_BYTES;
    const uint32_t bufu = smem_u32(buf);
    const int pass = stage >> 3, c = stage & 7;
    // A: 2 splits x 128 rows x 8 segs of 16B
#pragma unroll
    for (int it = tid; it < 2048; it += THREADS) {
        const int split = it >> 10, rem = it & 1023;
        const int row = rem >> 3, seg = rem & 7;
        const __nv_bfloat16* src = (split ? g_Al : g_Ah)
            + (size_t)(row0 + row) * DD + c * KC + seg * 8;
        const uint32_t dst = bufu + (split ? STG_AL : STG_AH) + swz((uint32_t)(row * 128 + seg * 16));
        CP_ASYNC16(dst, src);
    }
    // B: 2 splits x 256 rows x 8 segs
#pragma unroll
    for (int it = tid; it < 4096; it += THREADS) {
        const int split = it >> 11, rem = it & 2047;
        const int row = rem >> 3, seg = rem & 7;
        const __nv_bfloat16* src = (split ? g_Bl : g_Bh)
            + (size_t)(pass * 256 + row) * DD + c * KC + seg * 8;
        const uint32_t dst = bufu + (split ? STG_BL : STG_BH) + swz((uint32_t)(row * 128 + seg * 16));
        CP_ASYNC16(dst, src);
    }
}

__global__ __launch_bounds__(THREADS) void score_kernel(
    const float* __restrict__ bv, const float* __restrict__ bu,
    const float* __restrict__ wa, const float* __restrict__ ba)
{
    extern __shared__ char smem[];
    const uint32_t sb = smem_u32(smem);
    const int tid = threadIdx.x;
    const int w = tid >> 5, lane = tid & 31;
    const int wm = w & 3, wn = w >> 2;          // warp grid 4(M) x 4(N)
    const int g = lane >> 2, tig = lane & 3;
    const int sub = lane >> 3, lr = lane & 7;
    const int row0 = blockIdx.x * MROWS;

    float* sbias = (float*)(smem + SM_BIAS);
    float* slot = (float*)(smem + SM_SLOT);
    if (tid < 256) {
        sbias[tid] = bv[tid];
        sbias[256 + tid] = bu[tid];
        sbias[512 + tid] = wa[tid];
    }
    slot[tid] = 0.0f;
    slot[THREADS + tid] = 0.0f;

    fill_stage(smem, 0, 0, row0, tid);
    CP_COMMIT();

    for (int pass = 0; pass < NPASS; pass++) {
        float acc[2][8][4];
#pragma unroll
        for (int mt = 0; mt < 2; mt++)
#pragma unroll
            for (int nj = 0; nj < 8; nj++)
#pragma unroll
                for (int e = 0; e < 4; e++) acc[mt][nj][e] = 0.0f;

        for (int c = 0; c < NCHUNKS; c++) {
            const int st = pass * NCHUNKS + c;
            __syncthreads();    // all warps done with buf[(st)&1]'s previous tenant
            if (st + 1 < NSTAGES) {
                fill_stage(smem, (st + 1) & 1, st + 1, row0, tid);
                CP_COMMIT();
                asm volatile("cp.async.wait_group 1;" ::: "memory");
            } else {
                asm volatile("cp.async.wait_group 0;" ::: "memory");
            }
            __syncthreads();

            const uint32_t bufu = sb + (st & 1) * STG_BYTES;
#pragma unroll
            for (int ks = 0; ks < 4; ks++) {
                uint32_t a[2][2][4];
                const int kk = ks * 16 + (sub >> 1) * 8;
#pragma unroll
                for (int mt = 0; mt < 2; mt++) {
                    const int row = wm * 32 + mt * 16 + lr + (sub & 1) * 8;
                    const uint32_t off = swz((uint32_t)(row * 128 + kk * 2));
                    ldsm_x4(bufu + STG_AH + off, a[0][mt]);
                    ldsm_x4(bufu + STG_AL + off, a[1][mt]);
                }
#pragma unroll
                for (int ng = 0; ng < 4; ng++) {
                    const int nrow = wn * 64 + ng * 16 + lr + (sub & 1) * 8;
                    const uint32_t off = swz((uint32_t)(nrow * 128 + kk * 2));
                    uint32_t bh[4], bl[4];
                    ldsm_x4(bufu + STG_BH + off, bh);
                    ldsm_x4(bufu + STG_BL + off, bl);
#pragma unroll
                    for (int mt = 0; mt < 2; mt++) {
                        MMA_BF16(acc[mt][ng * 2 + 0], a[0][mt], bh[0], bh[2]);
                        MMA_BF16(acc[mt][ng * 2 + 0], a[0][mt], bl[0], bl[2]);
                        MMA_BF16(acc[mt][ng * 2 + 0], a[1][mt], bh[0], bh[2]);
                        MMA_BF16(acc[mt][ng * 2 + 1], a[0][mt], bh[1], bh[3]);
                        MMA_BF16(acc[mt][ng * 2 + 1], a[0][mt], bl[1], bl[3]);
                        MMA_BF16(acc[mt][ng * 2 + 1], a[1][mt], bh[1], bh[3]);
                    }
                }
            }
        }

        // ---- register-only epilogue: (c0,c1)=(v,u) same h, rows m / m+8 ----
        float rp[2][2] = { { 0.f, 0.f }, { 0.f, 0.f } };
#pragma unroll
        for (int mt = 0; mt < 2; mt++)
#pragma unroll
            for (int nj = 0; nj < 8; nj++) {
                const int h = pass * 128 + wn * 32 + nj * 4 + tig;
                const float bvh = sbias[h];
                const float buh = sbias[256 + h];
                const float wah = sbias[512 + h];
                const float g0 = tanhf(acc[mt][nj][0] + bvh)
                    * (1.0f / (1.0f + expf(-(acc[mt][nj][1] + buh)))) * wah;
                const float g1 = tanhf(acc[mt][nj][2] + bvh)
                    * (1.0f / (1.0f + expf(-(acc[mt][nj][3] + buh)))) * wah;
                rp[mt][0] += g0;
                rp[mt][1] += g1;
            }
#pragma unroll
        for (int mt = 0; mt < 2; mt++) {
            float v0 = rp[mt][0], v1 = rp[mt][1];
            v0 += __shfl_down_sync(0xffffffffu, v0, 2);
            v0 += __shfl_down_sync(0xffffffffu, v0, 1);
            v1 += __shfl_down_sync(0xffffffffu, v1, 2);
            v1 += __shfl_down_sync(0xffffffffu, v1, 1);
            if (tig == 0) {
                const int m = wm * 32 + mt * 16 + g;
                slot[m * 8 + wn] += v0;          // unique writer per (row, wn)
                slot[(m + 8) * 8 + wn] += v1;
            }
        }
    }

    __syncthreads();
    if (tid < MROWS) {
        float s = 0.f;
#pragma unroll
        for (int q = 0; q < 8; q++) s += slot[tid * 8 + q];
        g_raw[row0 + tid] = s + ba[0];
    }
}

// ==================== 2) softmax + orderable keys ====================
__global__ void softmax_keys_kernel(float* attn_out)
{
    const int b = blockIdx.x;
    const float* raw = g_raw + (size_t)b * NN;
    __shared__ float sm[32];
    __shared__ float s_bcast;
    const int tid = threadIdx.x, lane = tid & 31, wid = tid >> 5;

    float mx = -3.0e38f;
    for (int i = tid; i < NN; i += 1024) mx = fmaxf(mx, raw[i]);
    for (int o = 16; o > 0; o >>= 1) mx = fmaxf(mx, __shfl_down_sync(0xffffffffu, mx, o));
    if (lane == 0) sm[wid] = mx;
    __syncthreads();
    if (wid == 0) {
        float v = sm[lane];
        for (int o = 16; o > 0; o >>= 1) v = fmaxf(v, __shfl_down_sync(0xffffffffu, v, o));
        if (lane == 0) s_bcast = v;
    }
    __syncthreads();
    const float M = s_bcast;
    __syncthreads();

    float sum = 0.f;
    for (int i = tid; i < NN; i += 1024) sum += expf(raw[i] - M);
    for (int o = 16; o > 0; o >>= 1) sum += __shfl_down_sync(0xffffffffu, sum, o);
    if (lane == 0) sm[wid] = sum;
    __syncthreads();
    if (wid == 0) {
        float v = sm[lane];
        for (int o = 16; o > 0; o >>= 1) v += __shfl_down_sync(0xffffffffu, v, o);
        if (lane == 0) s_bcast = v;
    }
    __syncthreads();
    const float S = s_bcast;
    const float invS = 1.0f / S;

    for (int i = tid; i < NN; i += 1024) {
        const float r = raw[i];
        if (attn_out) attn_out[(size_t)b * NN + i] = expf(r - M) * invS;
        const unsigned bits = __float_as_uint(r);
        const unsigned u = (bits & 0x80000000u) ? ~bits : (bits | 0x80000000u);
        g_tkeys[(size_t)b * NN + i] = ~u;
    }
}

// ==================== scan helper ====================
__device__ __forceinline__ int block_excl_scan_1024(int val, int* ws)
{
    const int tid = threadIdx.x, lane = tid & 31, wid = tid >> 5;
    __syncthreads();
    int v = val;
#pragma unroll
    for (int o = 1; o < 32; o <<= 1) {
        int t = __shfl_up_sync(0xffffffffu, v, o);
        if (lane >= o) v += t;
    }
    if (lane == 31) ws[wid] = v;
    __syncthreads();
    if (wid == 0) {
        int s = ws[lane];
#pragma unroll
        for (int o = 1; o < 32; o <<= 1) {
            int t = __shfl_up_sync(0xffffffffu, s, o);
            if (lane >= o) s += t;
        }
        ws[lane] = s;
    }
    __syncthreads();
    const int wbase = (wid > 0) ? ws[wid - 1] : 0;
    return wbase + (v - val);
}

// ==================== 3) radix select ====================
template <int L, int NSEL>
__device__ void radix_select_body(const unsigned* __restrict__ keys, unsigned char* __restrict__ flags)
{
    __shared__ unsigned hist[256];
    __shared__ unsigned s_prefix;
    __shared__ int s_need;
    __shared__ int ws[32];

    const int tid = threadIdx.x;
    unsigned prefix = 0, maskbits = 0;
    int need = NSEL;

#pragma unroll
    for (int pass = 0; pass < 4; pass++) {
        const int shift = 24 - 8 * pass;
        if (tid < 256) hist[tid] = 0;
        __syncthreads();
        for (int i = tid; i < L; i += 1024) {
            const unsigned k = keys[i];
            if ((k & maskbits) == prefix) atomicAdd(&hist[(k >> shift) & 0xFFu], 1u);
        }
        __syncthreads();
        if (tid == 0) {
            unsigned run = 0; int d = 0;
            for (; d < 256; d++) {
                if (run + hist[d] >= (unsigned)need) break;
                run += hist[d];
            }
            s_prefix = prefix | ((unsigned)d << shift);
            s_need = need - (int)run;
        }
        __syncthreads();
        prefix = s_prefix;
        need = s_need;
        maskbits |= (0xFFu << shift);
        __syncthreads();
    }
    const unsigned T = prefix;

    const int chunk = (L + 1023) / 1024;
    const int start = tid * chunk;
    int cnt = 0;
    for (int e = 0; e < chunk; e++) {
        const int i = start + e;
        if (i < L && keys[i] == T) cnt++;
    }
    const int base = block_excl_scan_1024(cnt, ws);
    int seen = 0;
    for (int e = 0; e < chunk; e++) {
        const int i = start + e;
        if (i < L) {
            const unsigned k = keys[i];
            unsigned char f = 0;
            if (k < T) f = 1;
            else if (k == T) {
                if (base + seen < need) f = 1;
                seen++;
            }
            flags[i] = f;
        }
    }
}

__global__ void topk_select_kernel()
{
    radix_select_body<NN, N_TOP>(g_tkeys + (size_t)blockIdx.x * NN,
                                 g_topflag + (size_t)blockIdx.x * NN);
}
__global__ void rand_select_kernel()
{
    radix_select_body<N_REM, N_RAND>(g_rkeys + (size_t)blockIdx.x * N_REM,
                                     g_possel + (size_t)blockIdx.x * N_REM);
}

// ==================== 4) threefry (partitionable) ====================
__device__ __forceinline__ unsigned rotl32(unsigned x, int r) { return (x << r) | (x >> (32 - r)); }

__global__ void threefry_kernel()
{
    const int i = blockIdx.x * blockDim.x + threadIdx.x;
    if (i >= N_BITS) return;
    const unsigned k0 = 0u, k1 = 42u;
    const unsigned k2 = k0 ^ k1 ^ 0x1BD11BDAu;
    unsigned x0 = 0u;
    unsigned x1 = (unsigned)i;
    x0 += k0; x1 += k1;

#define TF_ROUND(r) { x0 += x1; x1 = rotl32(x1, r); x1 ^= x0; }
    TF_ROUND(13) TF_ROUND(15) TF_ROUND(26) TF_ROUND(6)
    x0 += k1; x1 += k2 + 1u;
    TF_ROUND(17) TF_ROUND(29) TF_ROUND(16) TF_ROUND(24)
    x0 += k2; x1 += k0 + 2u;
    TF_ROUND(13) TF_ROUND(15) TF_ROUND(26) TF_ROUND(6)
    x0 += k0; x1 += k1 + 3u;
    TF_ROUND(17) TF_ROUND(29) TF_ROUND(16) TF_ROUND(24)
    x0 += k1; x1 += k2 + 4u;
    TF_ROUND(13) TF_ROUND(15) TF_ROUND(26) TF_ROUND(6)
    x0 += k2; x1 += k0 + 5u;
#undef TF_ROUND

    g_rkeys[i] = (x0 ^ x1) >> 9;
}

// ==================== 5) combine ====================
__global__ void combine_kernel(float* idx_out)
{
    const int b = blockIdx.x;
    const unsigned char* __restrict__ top = g_topflag + (size_t)b * NN;
    const unsigned char* __restrict__ psel = g_possel + (size_t)b * N_REM;
    __shared__ int ws[32];
    const int tid = threadIdx.x;
    const int start = tid * 16;

    unsigned char tloc[16];
    int cntN = 0;
#pragma unroll
    for (int e = 0; e < 16; e++) {
        tloc[e] = top[start + e];
        if (!tloc[e]) cntN++;
    }
    const int baseN = block_excl_scan_1024(cntN, ws);

    int selbits = 0, cntS = 0, seenN = 0;
#pragma unroll
    for (int e = 0; e < 16; e++) {
        bool s;
        if (tloc[e]) s = true;
        else { s = (psel[baseN + seenN] != 0); seenN++; }
        if (s) { selbits |= (1 << e); cntS++; }
    }
    const int baseS = block_excl_scan_1024(cntS, ws);

    int seenS = 0;
#pragma unroll
    for (int e = 0; e < 16; e++) {
        if ((selbits >> e) & 1) {
            const int i = start + e;
            const int pos = baseS + seenS;
            seenS++;
            g_selidx[(size_t)b * K_SEL + pos] = i;
            if (idx_out) idx_out[(size_t)b * K_SEL + pos] = (float)i;
        }
    }
}

// ==================== 6) gather ====================
__global__ void gather_kernel(const float* __restrict__ feat, float* __restrict__ out)
{
    const int r = blockIdx.x;
    const int b = blockIdx.y;
    const int idx = g_selidx[(size_t)b * K_SEL + r];
    const float4* __restrict__ src = (const float4*)(feat + ((size_t)b * NN + idx) * DD);
    float4* __restrict__ dst = (float4*)(out + ((size_t)b * K_SEL + r) * DD);
    dst[threadIdx.x] = src[threadIdx.x];
}

// ==================== launch ====================
extern "C" void kernel_launch(void* const* d_in, const int* in_sizes, int n_in,
                              void* d_out, int out_size)
{
    int idx_feat = -1, idx_scalar = -1;
    int mats[2] = {-1, -1}; int nm = 0;
    int vecs[3] = {-1, -1, -1}; int nv = 0;
    for (int i = 0; i < n_in; i++) {
        const int s = in_sizes[i];
        if (s == 33554432) idx_feat = i;
        else if (s == 131072 && nm < 2) mats[nm++] = i;
        else if (s == 256 && nv < 3) vecs[nv++] = i;
        else if (s == 1) idx_scalar = i;
    }

    const float *feat, *Wv, *bv, *Wu, *bu, *wa, *ba;
    if (idx_feat >= 0 && nm == 2 && nv == 3 && idx_scalar >= 0) {
        feat = (const float*)d_in[idx_feat];
        ba   = (const float*)d_in[idx_scalar];
        wa   = (const float*)d_in[vecs[2]];
        bv   = (const float*)d_in[vecs[0]];
        bu   = (const float*)d_in[vecs[1]];
        if (idx_feat == 0) { Wv = (const float*)d_in[mats[0]]; Wu = (const float*)d_in[mats[1]]; }
        else               { Wu = (const float*)d_in[mats[0]]; Wv = (const float*)d_in[mats[1]]; }
    } else {
        feat = (const float*)d_in[0];
        Wv   = (const float*)d_in[1];
        bv   = (const float*)d_in[2];
        Wu   = (const float*)d_in[3];
        bu   = (const float*)d_in[4];
        wa   = (const float*)d_in[5];
        ba   = (const float*)d_in[6];
    }

    float* out = (float*)d_out;
    const long long SELN = (long long)BB * K_SEL * DD;
    const long long ATTN = (long long)BB * NN;
    const long long IDXN = (long long)BB * K_SEL;
    float* attn_out = ((long long)out_size >= SELN + ATTN) ? out + SELN : nullptr;
    float* idx_out  = ((long long)out_size >= SELN + ATTN + IDXN) ? out + SELN + ATTN : nullptr;

    static int attr_done = 0;
    if (!attr_done) {
        cudaFuncSetAttribute(score_kernel,
                             cudaFuncAttributeMaxDynamicSharedMemorySize, SMEM_TOTAL);
        attr_done = 1;
    }

    asplit_kernel<<<(int)(((size_t)BB * NN * DD / 4 + 255) / 256), 256>>>(feat);
    prepack_kernel<<<(512 * DD + 255) / 256, 256>>>(Wv, Wu);
    score_kernel<<<(BB * NN) / MROWS, THREADS, SMEM_TOTAL>>>(bv, bu, wa, ba);
    softmax_keys_kernel<<<BB, 1024>>>(attn_out);
    topk_select_kernel<<<BB, 1024>>>();
    threefry_kernel<<<(N_BITS + 255) / 256, 256>>>();
    rand_select_kernel<<<BB, 1024>>>();
    combine_kernel<<<BB, 1024>>>(idx_out);
    {
        dim3 grid(K_SEL, BB);
        gather_kernel<<<grid, 128>>>(feat, out);
    }
}

// round 17
// speedup vs baseline: 2.3764x; 1.0985x over previous
#include <cuda_runtime.h>
#include <cuda_bf16.h>
#include <cstdint>
#include <math.h>

// Problem constants
#define BB 4
#define NN 16384
#define DD 512
#define HH 256
#define K_SEL 11468
#define N_RAND 1146
#define N_TOP (K_SEL - N_RAND)       // 10322
#define N_REM (NN - N_TOP)           // 6062
#define N_BITS (BB * N_REM)          // 24248

#define MROWS 128                    // rows per CTA
#define KC 64                        // k per stage
#define NCHUNKS (DD / KC)            // 8 stages per CTA
#define THREADS 512

// per-stage buffer: AH 16K | AL 16K | BH 32K | BL 32K = 96KB
#define STG_BYTES 98304
#define STG_AH 0
#define STG_AL 16384
#define STG_BH 32768
#define STG_BL 65536
#define SM_BIAS (2 * STG_BYTES)              // 3*256 fp32
#define SM_SLOT (SM_BIAS + 3 * 256 * 4)      // 128*4 fp32
#define SMEM_TOTAL (SM_SLOT + 128 * 4 * 4)   // 201728

// -------------------- device scratch --------------------
__device__ float g_raw[BB * NN];
__device__ unsigned g_tkeys[BB * NN];
__device__ unsigned char g_topflag[BB * NN];
__device__ unsigned g_rkeys[BB * N_REM];
__device__ unsigned char g_possel[BB * N_REM];
__device__ int g_selidx[BB * K_SEL];
// A splits: row-major [65536][512] bf16
__device__ __nv_bfloat16 g_Ah[(size_t)BB * NN * DD];
__device__ __nv_bfloat16 g_Al[(size_t)BB * NN * DD];
// B^T interleaved stacked splits: row n in [0,512): pass p=n>>8, j=n&255,
//   h = p*128 + (j>>1); even j -> Wv col h, odd j -> Wu col h. B[n][k]=W[k][h].
__device__ __nv_bfloat16 g_Bh[512 * DD];
__device__ __nv_bfloat16 g_Bl[512 * DD];

__device__ __forceinline__ uint32_t smem_u32(const void* p) {
    uint32_t a;
    asm("{ .reg .u64 t; cvta.to.shared.u64 t, %1; cvt.u32.u64 %0, t; }" : "=r"(a) : "l"(p));
    return a;
}
__device__ __forceinline__ uint32_t swz(uint32_t off) { return off ^ ((off >> 3) & 0x70u); }

__device__ __forceinline__ void ldsm_x4(uint32_t addr, uint32_t* r) {
    asm volatile("ldmatrix.sync.aligned.m8n8.x4.shared.b16 {%0,%1,%2,%3}, [%4];"
        : "=r"(r[0]), "=r"(r[1]), "=r"(r[2]), "=r"(r[3]) : "r"(addr));
}
#define MMA_BF16(C, A, b0, b1) \
    asm volatile("mma.sync.aligned.m16n8k16.row.col.f32.bf16.bf16.f32 " \
        "{%0,%1,%2,%3}, {%4,%5,%6,%7}, {%8,%9}, {%0,%1,%2,%3};" \
        : "+f"((C)[0]), "+f"((C)[1]), "+f"((C)[2]), "+f"((C)[3]) \
        : "r"((A)[0]), "r"((A)[1]), "r"((A)[2]), "r"((A)[3]), "r"(b0), "r"(b1))
#define CP_ASYNC16(dst, src) \
    asm volatile("cp.async.cg.shared.global [%0], [%1], 16;" :: "r"(dst), "l"(src) : "memory")
#define CP_COMMIT() asm volatile("cp.async.commit_group;" ::: "memory")

// ==================== 0a) feature split prepack (+ g_raw zero-init) ========
__global__ void asplit_kernel(const float* __restrict__ feat)
{
    const size_t i4 = (size_t)blockIdx.x * blockDim.x + threadIdx.x;   // float4 index
    if (i4 < BB * NN) g_raw[i4] = 0.0f;
    if (i4 >= (size_t)BB * NN * DD / 4) return;
    const float4 v = ((const float4*)feat)[i4];
    const float xv[4] = { v.x, v.y, v.z, v.w };
    unsigned long long ph = 0, pl = 0;
#pragma unroll
    for (int e = 0; e < 4; e++) {
        const float x = xv[e];
        const __nv_bfloat16 h = __float2bfloat16(x);
        const float r = x - __bfloat162float(h);
        const __nv_bfloat16 l = __float2bfloat16(r);
        ph |= (unsigned long long)__bfloat16_as_ushort(h) << (16 * e);
        pl |= (unsigned long long)__bfloat16_as_ushort(l) << (16 * e);
    }
    ((unsigned long long*)g_Ah)[i4] = ph;
    ((unsigned long long*)g_Al)[i4] = pl;
}

// ==================== 0b) weight split/transpose prepack (interleaved) ====
__global__ void prepack_kernel(const float* __restrict__ Wv, const float* __restrict__ Wu)
{
    const int idx = blockIdx.x * blockDim.x + threadIdx.x;   // n*512 + k
    if (idx >= 512 * DD) return;
    const int n = idx >> 9, k = idx & 511;
    const int p = n >> 8, j = n & 255;
    const int h = p * 128 + (j >> 1);
    const float w = ((j & 1) == 0) ? Wv[(size_t)k * HH + h] : Wu[(size_t)k * HH + h];
    const __nv_bfloat16 hi = __float2bfloat16(w);
    const float r = w - __bfloat162float(hi);
    g_Bh[idx] = hi;
    g_Bl[idx] = __float2bfloat16(r);
}

// ==================== 1) scoring: cp.async double-buffered mma.sync ====
__device__ __forceinline__ void fill_stage(char* smem, int bufidx, int c, int pass, int row0, int tid)
{
    char* buf = smem + bufidx * STG_BYTES;
    const uint32_t bufu = smem_u32(buf);
    // A: 2 splits x 128 rows x 8 segs of 16B
#pragma unroll
    for (int it = tid; it < 2048; it += THREADS) {
        const int split = it >> 10, rem = it & 1023;
        const int row = rem >> 3, seg = rem & 7;
        const __nv_bfloat16* src = (split ? g_Al : g_Ah)
            + (size_t)(row0 + row) * DD + c * KC + seg * 8;
        const uint32_t dst = bufu + (split ? STG_AL : STG_AH) + swz((uint32_t)(row * 128 + seg * 16));
        CP_ASYNC16(dst, src);
    }
    // B: 2 splits x 256 rows x 8 segs
#pragma unroll
    for (int it = tid; it < 4096; it += THREADS) {
        const int split = it >> 11, rem = it & 2047;
        const int row = rem >> 3, seg = rem & 7;
        const __nv_bfloat16* src = (split ? g_Bl : g_Bh)
            + (size_t)(pass * 256 + row) * DD + c * KC + seg * 8;
        const uint32_t dst = bufu + (split ? STG_BL : STG_BH) + swz((uint32_t)(row * 128 + seg * 16));
        CP_ASYNC16(dst, src);
    }
}

__global__ __launch_bounds__(THREADS) void score_kernel(
    const float* __restrict__ bv, const float* __restrict__ bu,
    const float* __restrict__ wa, const float* __restrict__ ba)
{
    extern __shared__ char smem[];
    const uint32_t sb = smem_u32(smem);
    const int tid = threadIdx.x;
    const int w = tid >> 5, lane = tid & 31;
    const int wm = w & 3, wn = w >> 2;          // warp grid 4(M) x 4(N)
    const int g = lane >> 2, tig = lane & 3;
    const int sub = lane >> 3, lr = lane & 7;
    const int row0 = blockIdx.x * MROWS;
    const int pass = blockIdx.y;                // N-half

    float* sbias = (float*)(smem + SM_BIAS);
    float* slot = (float*)(smem + SM_SLOT);
    if (tid < 256) {
        sbias[tid] = bv[tid];
        sbias[256 + tid] = bu[tid];
        sbias[512 + tid] = wa[tid];
    }

    float acc[2][8][4];
#pragma unroll
    for (int mt = 0; mt < 2; mt++)
#pragma unroll
        for (int nj = 0; nj < 8; nj++)
#pragma unroll
            for (int e = 0; e < 4; e++) acc[mt][nj][e] = 0.0f;

    fill_stage(smem, 0, 0, pass, row0, tid);
    CP_COMMIT();

    for (int c = 0; c < NCHUNKS; c++) {
        __syncthreads();
        if (c + 1 < NCHUNKS) {
            fill_stage(smem, (c + 1) & 1, c + 1, pass, row0, tid);
            CP_COMMIT();
            asm volatile("cp.async.wait_group 1;" ::: "memory");
        } else {
            asm volatile("cp.async.wait_group 0;" ::: "memory");
        }
        __syncthreads();

        const uint32_t bufu = sb + (c & 1) * STG_BYTES;
#pragma unroll
        for (int ks = 0; ks < 4; ks++) {
            uint32_t a[2][2][4];
            const int kk = ks * 16 + (sub >> 1) * 8;
#pragma unroll
            for (int mt = 0; mt < 2; mt++) {
                const int row = wm * 32 + mt * 16 + lr + (sub & 1) * 8;
                const uint32_t off = swz((uint32_t)(row * 128 + kk * 2));
                ldsm_x4(bufu + STG_AH + off, a[0][mt]);
                ldsm_x4(bufu + STG_AL + off, a[1][mt]);
            }
#pragma unroll
            for (int ng = 0; ng < 4; ng++) {
                const int nrow = wn * 64 + ng * 16 + lr + (sub & 1) * 8;
                const uint32_t off = swz((uint32_t)(nrow * 128 + kk * 2));
                uint32_t bh[4], bl[4];
                ldsm_x4(bufu + STG_BH + off, bh);
                ldsm_x4(bufu + STG_BL + off, bl);
                // term-major issue order: per accumulator the term sequence is
                // (hh, hl, lh) exactly as before (bitwise-identical result),
                // but adjacent instructions hit different accumulators ->
                // 4 independent HMMA chains in flight.
#pragma unroll
                for (int mt = 0; mt < 2; mt++) {
                    MMA_BF16(acc[mt][ng * 2 + 0], a[0][mt], bh[0], bh[2]);
                    MMA_BF16(acc[mt][ng * 2 + 1], a[0][mt], bh[1], bh[3]);
                }
#pragma unroll
                for (int mt = 0; mt < 2; mt++) {
                    MMA_BF16(acc[mt][ng * 2 + 0], a[0][mt], bl[0], bl[2]);
                    MMA_BF16(acc[mt][ng * 2 + 1], a[0][mt], bl[1], bl[3]);
                }
#pragma unroll
                for (int mt = 0; mt < 2; mt++) {
                    MMA_BF16(acc[mt][ng * 2 + 0], a[1][mt], bh[0], bh[2]);
                    MMA_BF16(acc[mt][ng * 2 + 1], a[1][mt], bh[1], bh[3]);
                }
            }
        }
    }

    // ---- register-only epilogue: (c0,c1)=(v,u) same h, rows m / m+8 ----
    float rp[2][2] = { { 0.f, 0.f }, { 0.f, 0.f } };
#pragma unroll
    for (int mt = 0; mt < 2; mt++)
#pragma unroll
        for (int nj = 0; nj < 8; nj++) {
            const int h = pass * 128 + wn * 32 + nj * 4 + tig;
            const float bvh = sbias[h];
            const float buh = sbias[256 + h];
            const float wah = sbias[512 + h];
            const float g0 = tanhf(acc[mt][nj][0] + bvh)
                * (1.0f / (1.0f + expf(-(acc[mt][nj][1] + buh)))) * wah;
            const float g1 = tanhf(acc[mt][nj][2] + bvh)
                * (1.0f / (1.0f + expf(-(acc[mt][nj][3] + buh)))) * wah;
            rp[mt][0] += g0;
            rp[mt][1] += g1;
        }
#pragma unroll
    for (int mt = 0; mt < 2; mt++) {
        float v0 = rp[mt][0], v1 = rp[mt][1];
        v0 += __shfl_down_sync(0xffffffffu, v0, 2);
        v0 += __shfl_down_sync(0xffffffffu, v0, 1);
        v1 += __shfl_down_sync(0xffffffffu, v1, 2);
        v1 += __shfl_down_sync(0xffffffffu, v1, 1);
        if (tig == 0) {
            const int m = wm * 32 + mt * 16 + g;
            slot[m * 4 + wn] = v0;          // unique writer per (row, wn)
            slot[(m + 8) * 4 + wn] = v1;
        }
    }

    __syncthreads();
    if (tid < MROWS) {
        float s = slot[tid * 4] + slot[tid * 4 + 1] + slot[tid * 4 + 2] + slot[tid * 4 + 3];
        if (pass == 0) s += ba[0];
        atomicAdd(&g_raw[row0 + tid], s);   // exactly 2 contributions; fp32 add commutative
    }
}

// ==================== 2) softmax + orderable keys ====================
__global__ void softmax_keys_kernel(float* attn_out)
{
    const int b = blockIdx.x;
    const float* raw = g_raw + (size_t)b * NN;
    __shared__ float sm[32];
    __shared__ float s_bcast;
    const int tid = threadIdx.x, lane = tid & 31, wid = tid >> 5;

    float mx = -3.0e38f;
    for (int i = tid; i < NN; i += 1024) mx = fmaxf(mx, raw[i]);
    for (int o = 16; o > 0; o >>= 1) mx = fmaxf(mx, __shfl_down_sync(0xffffffffu, mx, o));
    if (lane == 0) sm[wid] = mx;
    __syncthreads();
    if (wid == 0) {
        float v = sm[lane];
        for (int o = 16; o > 0; o >>= 1) v = fmaxf(v, __shfl_down_sync(0xffffffffu, v, o));
        if (lane == 0) s_bcast = v;
    }
    __syncthreads();
    const float M = s_bcast;
    __syncthreads();

    float sum = 0.f;
    for (int i = tid; i < NN; i += 1024) sum += expf(raw[i] - M);
    for (int o = 16; o > 0; o >>= 1) sum += __shfl_down_sync(0xffffffffu, sum, o);
    if (lane == 0) sm[wid] = sum;
    __syncthreads();
    if (wid == 0) {
        float v = sm[lane];
        for (int o = 16; o > 0; o >>= 1) v += __shfl_down_sync(0xffffffffu, v, o);
        if (lane == 0) s_bcast = v;
    }
    __syncthreads();
    const float S = s_bcast;
    const float invS = 1.0f / S;

    for (int i = tid; i < NN; i += 1024) {
        const float r = raw[i];
        if (attn_out) attn_out[(size_t)b * NN + i] = expf(r - M) * invS;
        const unsigned bits = __float_as_uint(r);
        const unsigned u = (bits & 0x80000000u) ? ~bits : (bits | 0x80000000u);
        g_tkeys[(size_t)b * NN + i] = ~u;
    }
}

// ==================== scan helper ====================
__device__ __forceinline__ int block_excl_scan_1024(int val, int* ws)
{
    const int tid = threadIdx.x, lane = tid & 31, wid = tid >> 5;
    __syncthreads();
    int v = val;
#pragma unroll
    for (int o = 1; o < 32; o <<= 1) {
        int t = __shfl_up_sync(0xffffffffu, v, o);
        if (lane >= o) v += t;
    }
    if (lane == 31) ws[wid] = v;
    __syncthreads();
    if (wid == 0) {
        int s = ws[lane];
#pragma unroll
        for (int o = 1; o < 32; o <<= 1) {
            int t = __shfl_up_sync(0xffffffffu, s, o);
            if (lane >= o) s += t;
        }
        ws[lane] = s;
    }
    __syncthreads();
    const int wbase = (wid > 0) ? ws[wid - 1] : 0;
    return wbase + (v - val);
}

// ==================== 3) radix select ====================
template <int L, int NSEL>
__device__ void radix_select_body(const unsigned* __restrict__ keys, unsigned char* __restrict__ flags)
{
    __shared__ unsigned hist[256];
    __shared__ unsigned s_prefix;
    __shared__ int s_need;
    __shared__ int ws[32];

    const int tid = threadIdx.x;
    unsigned prefix = 0, maskbits = 0;
    int need = NSEL;

#pragma unroll
    for (int pass = 0; pass < 4; pass++) {
        const int shift = 24 - 8 * pass;
        if (tid < 256) hist[tid] = 0;
        __syncthreads();
        for (int i = tid; i < L; i += 1024) {
            const unsigned k = keys[i];
            if ((k & maskbits) == prefix) atomicAdd(&hist[(k >> shift) & 0xFFu], 1u);
        }
        __syncthreads();
        if (tid == 0) {
            unsigned run = 0; int d = 0;
            for (; d < 256; d++) {
                if (run + hist[d] >= (unsigned)need) break;
                run += hist[d];
            }
            s_prefix = prefix | ((unsigned)d << shift);
            s_need = need - (int)run;
        }
        __syncthreads();
        prefix = s_prefix;
        need = s_need;
        maskbits |= (0xFFu << shift);
        __syncthreads();
    }
    const unsigned T = prefix;

    const int chunk = (L + 1023) / 1024;
    const int start = tid * chunk;
    int cnt = 0;
    for (int e = 0; e < chunk; e++) {
        const int i = start + e;
        if (i < L && keys[i] == T) cnt++;
    }
    const int base = block_excl_scan_1024(cnt, ws);
    int seen = 0;
    for (int e = 0; e < chunk; e++) {
        const int i = start + e;
        if (i < L) {
            const unsigned k = keys[i];
            unsigned char f = 0;
            if (k < T) f = 1;
            else if (k == T) {
                if (base + seen < need) f = 1;
                seen++;
            }
            flags[i] = f;
        }
    }
}

__global__ void topk_select_kernel()
{
    radix_select_body<NN, N_TOP>(g_tkeys + (size_t)blockIdx.x * NN,
                                 g_topflag + (size_t)blockIdx.x * NN);
}
__global__ void rand_select_kernel()
{
    radix_select_body<N_REM, N_RAND>(g_rkeys + (size_t)blockIdx.x * N_REM,
                                     g_possel + (size_t)blockIdx.x * N_REM);
}

// ==================== 4) threefry (partitionable) ====================
__device__ __forceinline__ unsigned rotl32(unsigned x, int r) { return (x << r) | (x >> (32 - r)); }

__global__ void threefry_kernel()
{
    const int i = blockIdx.x * blockDim.x + threadIdx.x;
    if (i >= N_BITS) return;
    const unsigned k0 = 0u, k1 = 42u;
    const unsigned k2 = k0 ^ k1 ^ 0x1BD11BDAu;
    unsigned x0 = 0u;
    unsigned x1 = (unsigned)i;
    x0 += k0; x1 += k1;

#define TF_ROUND(r) { x0 += x1; x1 = rotl32(x1, r); x1 ^= x0; }
    TF_ROUND(13) TF_ROUND(15) TF_ROUND(26) TF_ROUND(6)
    x0 += k1; x1 += k2 + 1u;
    TF_ROUND(17) TF_ROUND(29) TF_ROUND(16) TF_ROUND(24)
    x0 += k2; x1 += k0 + 2u;
    TF_ROUND(13) TF_ROUND(15) TF_ROUND(26) TF_ROUND(6)
    x0 += k0; x1 += k1 + 3u;
    TF_ROUND(17) TF_ROUND(29) TF_ROUND(16) TF_ROUND(24)
    x0 += k1; x1 += k2 + 4u;
    TF_ROUND(13) TF_ROUND(15) TF_ROUND(26) TF_ROUND(6)
    x0 += k2; x1 += k0 + 5u;
#undef TF_ROUND

    g_rkeys[i] = (x0 ^ x1) >> 9;
}

// ==================== 5) combine ====================
__global__ void combine_kernel(float* idx_out)
{
    const int b = blockIdx.x;
    const unsigned char* __restrict__ top = g_topflag + (size_t)b * NN;
    const unsigned char* __restrict__ psel = g_possel + (size_t)b * N_REM;
    __shared__ int ws[32];
    const int tid = threadIdx.x;
    const int start = tid * 16;

    unsigned char tloc[16];
    int cntN = 0;
#pragma unroll
    for (int e = 0; e < 16; e++) {
        tloc[e] = top[start + e];
        if (!tloc[e]) cntN++;
    }
    const int baseN = block_excl_scan_1024(cntN, ws);

    int selbits = 0, cntS = 0, seenN = 0;
#pragma unroll
    for (int e = 0; e < 16; e++) {
        bool s;
        if (tloc[e]) s = true;
        else { s = (psel[baseN + seenN] != 0); seenN++; }
        if (s) { selbits |= (1 << e); cntS++; }
    }
    const int baseS = block_excl_scan_1024(cntS, ws);

    int seenS = 0;
#pragma unroll
    for (int e = 0; e < 16; e++) {
        if ((selbits >> e) & 1) {
            const int i = start + e;
            const int pos = baseS + seenS;
            seenS++;
            g_selidx[(size_t)b * K_SEL + pos] = i;
            if (idx_out) idx_out[(size_t)b * K_SEL + pos] = (float)i;
        }
    }
}

// ==================== 6) gather ====================
__global__ void gather_kernel(const float* __restrict__ feat, float* __restrict__ out)
{
    const int r = blockIdx.x;
    const int b = blockIdx.y;
    const int idx = g_selidx[(size_t)b * K_SEL + r];
    const float4* __restrict__ src = (const float4*)(feat + ((size_t)b * NN + idx) * DD);
    float4* __restrict__ dst = (float4*)(out + ((size_t)b * K_SEL + r) * DD);
    dst[threadIdx.x] = src[threadIdx.x];
}

// ==================== launch ====================
extern "C" void kernel_launch(void* const* d_in, const int* in_sizes, int n_in,
                              void* d_out, int out_size)
{
    int idx_feat = -1, idx_scalar = -1;
    int mats[2] = {-1, -1}; int nm = 0;
    int vecs[3] = {-1, -1, -1}; int nv = 0;
    for (int i = 0; i < n_in; i++) {
        const int s = in_sizes[i];
        if (s == 33554432) idx_feat = i;
        else if (s == 131072 && nm < 2) mats[nm++] = i;
        else if (s == 256 && nv < 3) vecs[nv++] = i;
        else if (s == 1) idx_scalar = i;
    }

    const float *feat, *Wv, *bv, *Wu, *bu, *wa, *ba;
    if (idx_feat >= 0 && nm == 2 && nv == 3 && idx_scalar >= 0) {
        feat = (const float*)d_in[idx_feat];
        ba   = (const float*)d_in[idx_scalar];
        wa   = (const float*)d_in[vecs[2]];
        bv   = (const float*)d_in[vecs[0]];
        bu   = (const float*)d_in[vecs[1]];
        if (idx_feat == 0) { Wv = (const float*)d_in[mats[0]]; Wu = (const float*)d_in[mats[1]]; }
        else               { Wu = (const float*)d_in[mats[0]]; Wv = (const float*)d_in[mats[1]]; }
    } else {
        feat = (const float*)d_in[0];
        Wv   = (const float*)d_in[1];
        bv   = (const float*)d_in[2];
        Wu   = (const float*)d_in[3];
        bu   = (const float*)d_in[4];
        wa   = (const float*)d_in[5];
        ba   = (const float*)d_in[6];
    }

    float* out = (float*)d_out;
    const long long SELN = (long long)BB * K_SEL * DD;
    const long long ATTN = (long long)BB * NN;
    const long long IDXN = (long long)BB * K_SEL;
    float* attn_out = ((long long)out_size >= SELN + ATTN) ? out + SELN : nullptr;
    float* idx_out  = ((long long)out_size >= SELN + ATTN + IDXN) ? out + SELN + ATTN : nullptr;

    static int attr_done = 0;
    if (!attr_done) {
        cudaFuncSetAttribute(score_kernel,
                             cudaFuncAttributeMaxDynamicSharedMemorySize, SMEM_TOTAL);
        attr_done = 1;
    }

    asplit_kernel<<<(int)(((size_t)BB * NN * DD / 4 + 255) / 256), 256>>>(feat);
    prepack_kernel<<<(512 * DD + 255) / 256, 256>>>(Wv, Wu);
    {
        dim3 grid((BB * NN) / MROWS, 2);    // 512 row-tiles x 2 N-halves
        score_kernel<<<grid, THREADS, SMEM_TOTAL>>>(bv, bu, wa, ba);
    }
    softmax_keys_kernel<<<BB, 1024>>>(attn_out);
    topk_select_kernel<<<BB, 1024>>>();
    threefry_kernel<<<(N_BITS + 255) / 256, 256>>>();
    rand_select_kernel<<<BB, 1024>>>();
    combine_kernel<<<BB, 1024>>>(idx_out);
    {
        dim3 grid(K_SEL, BB);
        gather_kernel<<<grid, 128>>>(feat, out);
    }
}